// round 14
// baseline (speedup 1.0000x reference)
#include <cuda_runtime.h>
#include <cuda_fp16.h>

#define N_NODES 60000
#define N_EDGES 1200000
#define D 64
#define CAP 128                      // bucket capacity per node (max deg ~50)

// ---------------- scratch (no allocations allowed; zero-init at load) -------
__device__ int     g_fill[N_NODES];          // cursor; re-zeroed each replay
__device__ int     g_degv[N_NODES];          // PADDED degree (multiple of 8)
__device__ int     g_edges[N_NODES * CAP];   // bucketed PRESCALED offs (src*32)
__device__ float   g_dinv[N_NODES];          // 1/sqrt(max(deg,1))
__device__ float   g_dsq [N_NODES];          // sqrt(max(deg,1))
// row N_NODES is a permanent zero row (never written) used by sentinel pads
__device__ __half2 g_xs0[(N_NODES + 1) * 32];  // X0 * dinv (fp16)
__device__ __half2 g_xs1[(N_NODES + 1) * 32];  // X1 * dinv (fp16)

// ---------------- build: atomic fill + float4 relu(X0) stream ---------------
__global__ void k_fill_relu(const int* __restrict__ src, const int* __restrict__ dst,
                            const float* __restrict__ feat, float* __restrict__ out,
                            int e, int n) {
    int i = blockIdx.x * blockDim.x + threadIdx.x;
    if (i < e) {
        int d   = dst[i];
        int pos = atomicAdd(&g_fill[d], 1);
        if (pos < CAP) g_edges[d * CAP + pos] = src[i] * 32;   // half2-unit offset
    }
    if (i < n * 16) {                     // float4 per thread: out[:,0:64]=relu(feat)
        int row = i >> 4;
        int q   = i & 15;
        float4 f = ((const float4*)feat)[i];
        ((float4*)(out + (size_t)row * 192))[q] =
            make_float4(fmaxf(f.x, 0.f), fmaxf(f.y, 0.f),
                        fmaxf(f.z, 0.f), fmaxf(f.w, 0.f));
    }
}

// ---------------- scale: dinv/pad from cursor; xs0 = fp16(feat*dinv);
//                  pad bucket to multiple of 8 with sentinel zero-row --------
__global__ void k_scale(const float* __restrict__ feat, int n) {
    int i = blockIdx.x * blockDim.x + threadIdx.x;
    if (i >= n * 32) return;
    int row  = i >> 5;
    int lane = i & 31;
    int deg = g_fill[row];                        // all 32 lanes read it
    deg = min(deg, CAP);
    int pad = min((deg + 7) & ~7, CAP);
    float df = (float)(deg > 0 ? deg : 1);
    float di = rsqrtf(df);
    float2 f = ((const float2*)feat)[i];
    g_xs0[i] = __floats2half2_rn(f.x * di, f.y * di);
    if (lane < pad - deg)                         // <=7 sentinel pads
        g_edges[row * CAP + deg + lane] = N_NODES * 32;
    __syncwarp();                                 // all lanes done with g_fill[row]
    if (lane == 0) {                              // warp owns the row exclusively
        g_degv[row] = pad;
        g_dinv[row] = di;
        g_dsq[row]  = sqrtf(df);
        g_fill[row] = 0;                          // ready for next graph replay
    }
}

// ---------------- gather: TWO nodes per warp (16 lanes each), uint2 rows;
//                  batched 8-load chunks + fp16 tree reduce ------------------
__device__ __forceinline__ __half2 u2h(unsigned u) { return *(__half2*)&u; }

__device__ __forceinline__ void gather2(int node, int pad, int padmax, int sl,
                                        unsigned gmask, const __half2* __restrict__ xs,
                                        float2& a01, float2& a23) {
    const int* bucket = &g_edges[node * CAP];
    for (int j = 0; j < padmax; j += 16) {
        int idx = j + sl;
        int s = __ldg(&bucket[idx < CAP ? idx : 0]);    // clamped, in-bounds
        #pragma unroll
        for (int k = 0; k < 16; k += 8) {
            if (j + k < pad) {                          // uniform per 16-lane group
                // phase 1: 8 independent LDG.64s, no consumer in between
                int b0 = __shfl_sync(gmask, s, k + 0, 16);
                int b1 = __shfl_sync(gmask, s, k + 1, 16);
                int b2 = __shfl_sync(gmask, s, k + 2, 16);
                int b3 = __shfl_sync(gmask, s, k + 3, 16);
                int b4 = __shfl_sync(gmask, s, k + 4, 16);
                int b5 = __shfl_sync(gmask, s, k + 5, 16);
                int b6 = __shfl_sync(gmask, s, k + 6, 16);
                int b7 = __shfl_sync(gmask, s, k + 7, 16);
                uint2 v0 = __ldg((const uint2*)(xs + b0) + sl);
                uint2 v1 = __ldg((const uint2*)(xs + b1) + sl);
                uint2 v2 = __ldg((const uint2*)(xs + b2) + sl);
                uint2 v3 = __ldg((const uint2*)(xs + b3) + sl);
                uint2 v4 = __ldg((const uint2*)(xs + b4) + sl);
                uint2 v5 = __ldg((const uint2*)(xs + b5) + sl);
                uint2 v6 = __ldg((const uint2*)(xs + b6) + sl);
                uint2 v7 = __ldg((const uint2*)(xs + b7) + sl);
                // phase 2: depth-3 fp16 tree per component, fp32 flush
                __half2 x01 = __hadd2(u2h(v0.x), u2h(v1.x));
                __half2 x23 = __hadd2(u2h(v2.x), u2h(v3.x));
                __half2 x45 = __hadd2(u2h(v4.x), u2h(v5.x));
                __half2 x67 = __hadd2(u2h(v6.x), u2h(v7.x));
                __half2 y01 = __hadd2(u2h(v0.y), u2h(v1.y));
                __half2 y23 = __hadd2(u2h(v2.y), u2h(v3.y));
                __half2 y45 = __hadd2(u2h(v4.y), u2h(v5.y));
                __half2 y67 = __hadd2(u2h(v6.y), u2h(v7.y));
                __half2 xt = __hadd2(__hadd2(x01, x23), __hadd2(x45, x67));
                __half2 yt = __hadd2(__hadd2(y01, y23), __hadd2(y45, y67));
                float2 fx = __half22float2(xt);
                float2 fy = __half22float2(yt);
                a01.x += fx.x; a01.y += fx.y;
                a23.x += fy.x; a23.y += fy.y;
            }
        }
    }
}

// X1 = -rn*h + (rn-1)*X0 ; writes xs1 = fp16(X1*dinv), out[:,64:128]=relu(X1)
__global__ void __launch_bounds__(128, 12)
k_apply1(const float* __restrict__ feat, const float* __restrict__ lam,
         float* __restrict__ out, int n) {
    int wp   = (blockIdx.x * blockDim.x + threadIdx.x) >> 5;
    int lane = threadIdx.x & 31;
    int g    = lane >> 4;
    int sl   = lane & 15;
    int w    = wp * 2 + g;
    if (w >= n) return;
    unsigned gmask = 0xffffu << (g * 16);
    float rn = 2.0f / __ldg(lam);
    float di = g_dinv[w];
    int  pad = __ldg(&g_degv[w]);
    int  padmax = max(pad, __shfl_xor_sync(0xffffffffu, pad, 16));
    float2 a01 = make_float2(0.f, 0.f), a23 = make_float2(0.f, 0.f);
    gather2(w, pad, padmax, sl, gmask, g_xs0, a01, a23);
    float4 x0 = ((const float4*)feat)[w * 16 + sl];
    float c1 = rn - 1.0f;
    float4 x1;
    x1.x = -rn * (a01.x * di) + x0.x * c1;
    x1.y = -rn * (a01.y * di) + x0.y * c1;
    x1.z = -rn * (a23.x * di) + x0.z * c1;
    x1.w = -rn * (a23.y * di) + x0.w * c1;
    __half2 p0 = __floats2half2_rn(x1.x * di, x1.y * di);
    __half2 p1 = __floats2half2_rn(x1.z * di, x1.w * di);
    ((uint2*)g_xs1)[w * 16 + sl] = make_uint2(*(unsigned*)&p0, *(unsigned*)&p1);
    ((float4*)(out + (size_t)w * 192 + 64))[sl] =
        make_float4(fmaxf(x1.x, 0.f), fmaxf(x1.y, 0.f),
                    fmaxf(x1.z, 0.f), fmaxf(x1.w, 0.f));
}

// X2 = -2rn*h + 2(rn-1)*X1 - X0 ; X1 recovered as fp16(xs1)*sqrt(deg)
__global__ void __launch_bounds__(128, 12)
k_apply2(const float* __restrict__ feat, const float* __restrict__ lam,
         float* __restrict__ out, int n) {
    int wp   = (blockIdx.x * blockDim.x + threadIdx.x) >> 5;
    int lane = threadIdx.x & 31;
    int g    = lane >> 4;
    int sl   = lane & 15;
    int w    = wp * 2 + g;
    if (w >= n) return;
    unsigned gmask = 0xffffu << (g * 16);
    float rn = 2.0f / __ldg(lam);
    float di = g_dinv[w];
    float ds = g_dsq[w];
    int  pad = __ldg(&g_degv[w]);
    int  padmax = max(pad, __shfl_xor_sync(0xffffffffu, pad, 16));
    float2 a01 = make_float2(0.f, 0.f), a23 = make_float2(0.f, 0.f);
    gather2(w, pad, padmax, sl, gmask, g_xs1, a01, a23);
    float4 x0 = ((const float4*)feat)[w * 16 + sl];
    uint2 xv = ((const uint2*)g_xs1)[w * 16 + sl];
    float2 s0 = __half22float2(*(__half2*)&xv.x);
    float2 s1 = __half22float2(*(__half2*)&xv.y);
    float c2 = 2.0f * (rn - 1.0f);
    float r2 = -2.0f * rn;
    float4 x2;
    x2.x = r2 * (a01.x * di) + c2 * (s0.x * ds) - x0.x;
    x2.y = r2 * (a01.y * di) + c2 * (s0.y * ds) - x0.y;
    x2.z = r2 * (a23.x * di) + c2 * (s1.x * ds) - x0.z;
    x2.w = r2 * (a23.y * di) + c2 * (s1.y * ds) - x0.w;
    ((float4*)(out + (size_t)w * 192 + 128))[sl] =
        make_float4(fmaxf(x2.x, 0.f), fmaxf(x2.y, 0.f),
                    fmaxf(x2.z, 0.f), fmaxf(x2.w, 0.f));
}

// ---------------- launch ----------------
extern "C" void kernel_launch(void* const* d_in, const int* in_sizes, int n_in,
                              void* d_out, int out_size) {
    const float* feat = (const float*)d_in[0];
    const int*   src  = (const int*)d_in[1];
    const int*   dst  = (const int*)d_in[2];
    const float* lam  = (const float*)d_in[3];
    float* out = (float*)d_out;

    int n = in_sizes[0] / D;     // 60000
    int e = in_sizes[1];         // 1200000

    int fmax = (n * 16 > e) ? n * 16 : e;
    k_fill_relu<<<(fmax + 255) / 256, 256>>>(src, dst, feat, out, e, n);

    int sthreads = n * 32;
    k_scale <<<(sthreads + 255) / 256, 256>>>(feat, n);

    int athreads = ((n + 1) / 2) * 32;            // 2 nodes per warp
    k_apply1<<<(athreads + 127) / 128, 128>>>(feat, lam, out, n);
    k_apply2<<<(athreads + 127) / 128, 128>>>(feat, lam, out, n);
}

// round 15
// speedup vs baseline: 1.2370x; 1.2370x over previous
#include <cuda_runtime.h>
#include <cuda_fp16.h>

#define N_NODES 60000
#define N_EDGES 1200000
#define D 64
#define CAP 128                      // bucket capacity per node (max deg ~50)

// ---------------- scratch (no allocations allowed; zero-init at load) -------
__device__ int     g_fill[N_NODES];          // cursor; re-zeroed each replay
__device__ int     g_degv[N_NODES];          // PADDED degree (multiple of 8)
__device__ int     g_edges[N_NODES * CAP];   // bucketed PRESCALED offs (src*32)
__device__ float   g_dinv[N_NODES];          // 1/sqrt(max(deg,1))
__device__ float   g_dsq [N_NODES];          // sqrt(max(deg,1))
// row N_NODES is a permanent zero row (never written) used by sentinel pads
__device__ __half2 g_xs0[(N_NODES + 1) * 32];  // X0 * dinv (fp16)
__device__ __half2 g_xs1[(N_NODES + 1) * 32];  // X1 * dinv (fp16)

// ---------------- build: coarsened atomic fill (2 edges/thread) +
//                  float4 relu(X0) stream ------------------------------------
__global__ void k_fill_relu(const int* __restrict__ src, const int* __restrict__ dst,
                            const float* __restrict__ feat, float* __restrict__ out,
                            int e, int n) {
    int i = blockIdx.x * blockDim.x + threadIdx.x;
    int eh = (e + 1) >> 1;
    if (i < eh) {                         // two independent edges per thread
        int d0 = dst[i];
        int s0 = src[i] * 32;
        int j2 = i + eh;
        int p0 = atomicAdd(&g_fill[d0], 1);
        if (j2 < e) {
            int d1 = dst[j2];
            int s1 = src[j2] * 32;
            int p1 = atomicAdd(&g_fill[d1], 1);
            if (p1 < CAP) g_edges[d1 * CAP + p1] = s1;
        }
        if (p0 < CAP) g_edges[d0 * CAP + p0] = s0;
    }
    if (i < n * 16) {                     // float4 per thread: out[:,0:64]=relu(feat)
        int row = i >> 4;
        int q   = i & 15;
        float4 f = ((const float4*)feat)[i];
        ((float4*)(out + (size_t)row * 192))[q] =
            make_float4(fmaxf(f.x, 0.f), fmaxf(f.y, 0.f),
                        fmaxf(f.z, 0.f), fmaxf(f.w, 0.f));
    }
}

// ---------------- scale: dinv/pad from cursor; xs0 = fp16(feat*dinv);
//                  pad bucket to multiple of 8 with sentinel zero-row --------
__global__ void k_scale(const float* __restrict__ feat, int n) {
    int i = blockIdx.x * blockDim.x + threadIdx.x;
    if (i >= n * 32) return;
    int row  = i >> 5;
    int lane = i & 31;
    int deg = g_fill[row];                        // all 32 lanes read it
    deg = min(deg, CAP);
    int pad = min((deg + 7) & ~7, CAP);
    float df = (float)(deg > 0 ? deg : 1);
    float di = rsqrtf(df);
    float2 f = ((const float2*)feat)[i];
    g_xs0[i] = __floats2half2_rn(f.x * di, f.y * di);
    if (lane < pad - deg)                         // <=7 sentinel pads
        g_edges[row * CAP + deg + lane] = N_NODES * 32;
    __syncwarp();                                 // all lanes done with g_fill[row]
    if (lane == 0) {                              // warp owns the row exclusively
        g_degv[row] = pad;
        g_dinv[row] = di;
        g_dsq[row]  = sqrtf(df);
        g_fill[row] = 0;                          // ready for next graph replay
    }
}

// ---------------- gather: TWO nodes per warp (16 lanes each), uint2 rows ----
// sl = lane & 15 covers feats [4*sl, 4*sl+4). Outer loop runs to padmax
// (warp-converged); per-8-chunk guards are uniform within each 16-lane group;
// shuffles are width-16 with the group's mask (legal under half-warp split).
__device__ __forceinline__ void gather2(int node, int pad, int padmax, int sl,
                                        unsigned gmask, const __half2* __restrict__ xs,
                                        float2& a01, float2& a23) {
    const int* bucket = &g_edges[node * CAP];
    const __half2 hz = __float2half2_rn(0.f);
    for (int j = 0; j < padmax; j += 16) {
        int idx = j + sl;
        int s = __ldg(&bucket[idx < CAP ? idx : 0]);    // clamped, in-bounds
        #pragma unroll
        for (int k = 0; k < 16; k += 8) {
            if (j + k < pad) {                          // uniform per group
                __half2 h0 = hz, h1 = hz;
                #pragma unroll
                for (int kk = 0; kk < 8; kk++) {
                    int sk = __shfl_sync(gmask, s, k + kk, 16);
                    uint2 v = __ldg((const uint2*)(xs + sk) + sl);
                    h0 = __hadd2(h0, *(__half2*)&v.x);
                    h1 = __hadd2(h1, *(__half2*)&v.y);
                }
                float2 f0 = __half22float2(h0);
                float2 f1 = __half22float2(h1);
                a01.x += f0.x; a01.y += f0.y;
                a23.x += f1.x; a23.y += f1.y;
            }
        }
    }
}

// X1 = -rn*h + (rn-1)*X0 ; writes xs1 = fp16(X1*dinv), out[:,64:128]=relu(X1)
__global__ void k_apply1(const float* __restrict__ feat, const float* __restrict__ lam,
                         float* __restrict__ out, int n) {
    int wp   = (blockIdx.x * blockDim.x + threadIdx.x) >> 5;
    int lane = threadIdx.x & 31;
    int g    = lane >> 4;
    int sl   = lane & 15;
    int w    = wp * 2 + g;
    if (w >= n) return;
    unsigned gmask = 0xffffu << (g * 16);
    float rn = 2.0f / __ldg(lam);
    float di = g_dinv[w];
    int  pad = __ldg(&g_degv[w]);
    int  padmax = max(pad, __shfl_xor_sync(0xffffffffu, pad, 16));
    float2 a01 = make_float2(0.f, 0.f), a23 = make_float2(0.f, 0.f);
    gather2(w, pad, padmax, sl, gmask, g_xs0, a01, a23);
    float4 x0 = ((const float4*)feat)[w * 16 + sl];
    float c1 = rn - 1.0f;
    float4 x1;
    x1.x = -rn * (a01.x * di) + x0.x * c1;
    x1.y = -rn * (a01.y * di) + x0.y * c1;
    x1.z = -rn * (a23.x * di) + x0.z * c1;
    x1.w = -rn * (a23.y * di) + x0.w * c1;
    __half2 p0 = __floats2half2_rn(x1.x * di, x1.y * di);
    __half2 p1 = __floats2half2_rn(x1.z * di, x1.w * di);
    ((uint2*)g_xs1)[w * 16 + sl] = make_uint2(*(unsigned*)&p0, *(unsigned*)&p1);
    ((float4*)(out + (size_t)w * 192 + 64))[sl] =
        make_float4(fmaxf(x1.x, 0.f), fmaxf(x1.y, 0.f),
                    fmaxf(x1.z, 0.f), fmaxf(x1.w, 0.f));
}

// X2 = -2rn*h + 2(rn-1)*X1 - X0 ; X1 recovered as fp16(xs1)*sqrt(deg)
__global__ void k_apply2(const float* __restrict__ feat, const float* __restrict__ lam,
                         float* __restrict__ out, int n) {
    int wp   = (blockIdx.x * blockDim.x + threadIdx.x) >> 5;
    int lane = threadIdx.x & 31;
    int g    = lane >> 4;
    int sl   = lane & 15;
    int w    = wp * 2 + g;
    if (w >= n) return;
    unsigned gmask = 0xffffu << (g * 16);
    float rn = 2.0f / __ldg(lam);
    float di = g_dinv[w];
    float ds = g_dsq[w];
    int  pad = __ldg(&g_degv[w]);
    int  padmax = max(pad, __shfl_xor_sync(0xffffffffu, pad, 16));
    float2 a01 = make_float2(0.f, 0.f), a23 = make_float2(0.f, 0.f);
    gather2(w, pad, padmax, sl, gmask, g_xs1, a01, a23);
    float4 x0 = ((const float4*)feat)[w * 16 + sl];
    uint2 xv = ((const uint2*)g_xs1)[w * 16 + sl];
    float2 s0 = __half22float2(*(__half2*)&xv.x);
    float2 s1 = __half22float2(*(__half2*)&xv.y);
    float c2 = 2.0f * (rn - 1.0f);
    float r2 = -2.0f * rn;
    float4 x2;
    x2.x = r2 * (a01.x * di) + c2 * (s0.x * ds) - x0.x;
    x2.y = r2 * (a01.y * di) + c2 * (s0.y * ds) - x0.y;
    x2.z = r2 * (a23.x * di) + c2 * (s1.x * ds) - x0.z;
    x2.w = r2 * (a23.y * di) + c2 * (s1.y * ds) - x0.w;
    ((float4*)(out + (size_t)w * 192 + 128))[sl] =
        make_float4(fmaxf(x2.x, 0.f), fmaxf(x2.y, 0.f),
                    fmaxf(x2.z, 0.f), fmaxf(x2.w, 0.f));
}

// ---------------- launch ----------------
extern "C" void kernel_launch(void* const* d_in, const int* in_sizes, int n_in,
                              void* d_out, int out_size) {
    const float* feat = (const float*)d_in[0];
    const int*   src  = (const int*)d_in[1];
    const int*   dst  = (const int*)d_in[2];
    const float* lam  = (const float*)d_in[3];
    float* out = (float*)d_out;

    int n = in_sizes[0] / D;     // 60000
    int e = in_sizes[1];         // 1200000

    int eh = (e + 1) >> 1;
    int fmax = (n * 16 > eh) ? n * 16 : eh;
    k_fill_relu<<<(fmax + 255) / 256, 256>>>(src, dst, feat, out, e, n);

    int sthreads = n * 32;
    k_scale <<<(sthreads + 255) / 256, 256>>>(feat, n);

    int athreads = ((n + 1) / 2) * 32;            // 2 nodes per warp
    k_apply1<<<(athreads + 127) / 128, 128>>>(feat, lam, out, n);
    k_apply2<<<(athreads + 127) / 128, 128>>>(feat, lam, out, n);
}

// round 17
// speedup vs baseline: 1.3198x; 1.0670x over previous
#include <cuda_runtime.h>
#include <cuda_fp16.h>

#define N_NODES 60000
#define N_EDGES 1200000
#define D 64
#define CAP 128                      // bucket capacity per node (max deg ~50)

// ---------------- scratch (no allocations allowed; zero-init at load) -------
__device__ int     g_fill[N_NODES];          // cursor; re-zeroed each replay
__device__ int     g_degv[N_NODES];          // PADDED degree (multiple of 8)
__device__ int     g_edges[N_NODES * CAP];   // bucketed PRESCALED offs (src*32)
__device__ float   g_dinv[N_NODES];          // 1/sqrt(max(deg,1))
__device__ float   g_dsq [N_NODES];          // sqrt(max(deg,1))
// row N_NODES is a permanent zero row (never written) used by sentinel pads
__device__ __half2 g_xs0[(N_NODES + 1) * 32];  // X0 * dinv (fp16)
__device__ __half2 g_xs1[(N_NODES + 1) * 32];  // X1 * dinv (fp16)

__device__ __forceinline__ __half2 u2h(unsigned u) { return *(__half2*)&u; }

// ---------------- build: coarsened atomic fill (2 edges/thread) +
//                  float4 relu(X0) stream ------------------------------------
__global__ void k_fill_relu(const int* __restrict__ src, const int* __restrict__ dst,
                            const float* __restrict__ feat, float* __restrict__ out,
                            int e, int n) {
    int i = blockIdx.x * blockDim.x + threadIdx.x;
    int eh = (e + 1) >> 1;
    if (i < eh) {                         // two independent edges per thread
        int d0 = dst[i];
        int s0 = src[i] * 32;
        int j2 = i + eh;
        int p0 = atomicAdd(&g_fill[d0], 1);
        if (j2 < e) {
            int d1 = dst[j2];
            int s1 = src[j2] * 32;
            int p1 = atomicAdd(&g_fill[d1], 1);
            if (p1 < CAP) g_edges[d1 * CAP + p1] = s1;
        }
        if (p0 < CAP) g_edges[d0 * CAP + p0] = s0;
    }
    if (i < n * 16) {                     // float4 per thread: out[:,0:64]=relu(feat)
        int row = i >> 4;
        int q   = i & 15;
        float4 f = ((const float4*)feat)[i];
        ((float4*)(out + (size_t)row * 192))[q] =
            make_float4(fmaxf(f.x, 0.f), fmaxf(f.y, 0.f),
                        fmaxf(f.z, 0.f), fmaxf(f.w, 0.f));
    }
}

// ---------------- scale: dinv/pad from cursor; xs0 = fp16(feat*dinv);
//                  pad bucket to multiple of 8 with sentinel zero-row --------
__global__ void k_scale(const float* __restrict__ feat, int n) {
    int i = blockIdx.x * blockDim.x + threadIdx.x;
    if (i >= n * 32) return;
    int row  = i >> 5;
    int lane = i & 31;
    int deg = g_fill[row];                        // all 32 lanes read it
    deg = min(deg, CAP);
    int pad = min((deg + 7) & ~7, CAP);
    float df = (float)(deg > 0 ? deg : 1);
    float di = rsqrtf(df);
    float2 f = ((const float2*)feat)[i];
    g_xs0[i] = __floats2half2_rn(f.x * di, f.y * di);
    if (lane < pad - deg)                         // <=7 sentinel pads
        g_edges[row * CAP + deg + lane] = N_NODES * 32;
    __syncwarp();                                 // all lanes done with g_fill[row]
    if (lane == 0) {                              // warp owns the row exclusively
        g_degv[row] = pad;
        g_dinv[row] = di;
        g_dsq[row]  = sqrtf(df);
        g_fill[row] = 0;                          // ready for next graph replay
    }
}

// ---------------- gather: FOUR nodes per warp (8 lanes each), uint4 rows ----
// g = lane>>3 selects node; sl = lane&7 covers feats [8*sl, 8*sl+8).
// One outer step = one 8-edge chunk (8 idx from 8 lanes, width-8 shuffles).
// Four independent fp16 chains per warp -> ~2x outstanding loads vs 2-node.
__device__ __forceinline__ void gather4(int node, int pad, int padmax, int sl,
                                        unsigned gmask, const __half2* __restrict__ xs,
                                        float2& a0, float2& a1,
                                        float2& a2, float2& a3) {
    const int* bucket = &g_edges[node * CAP];
    const __half2 hz = __float2half2_rn(0.f);
    for (int j = 0; j < padmax; j += 8) {
        if (j < pad) {                            // uniform per 8-lane group
            int s = __ldg(&bucket[j + sl]);       // 8 idx for this chunk
            __half2 c0 = hz, c1 = hz, c2 = hz, c3 = hz;
            #pragma unroll
            for (int e = 0; e < 8; e++) {
                int sk = __shfl_sync(gmask, s, e, 8);
                uint4 v = __ldg((const uint4*)(xs + sk) + sl);
                c0 = __hadd2(c0, u2h(v.x));
                c1 = __hadd2(c1, u2h(v.y));
                c2 = __hadd2(c2, u2h(v.z));
                c3 = __hadd2(c3, u2h(v.w));
            }
            float2 f;
            f = __half22float2(c0); a0.x += f.x; a0.y += f.y;
            f = __half22float2(c1); a1.x += f.x; a1.y += f.y;
            f = __half22float2(c2); a2.x += f.x; a2.y += f.y;
            f = __half22float2(c3); a3.x += f.x; a3.y += f.y;
        }
    }
}

// X1 = -rn*h + (rn-1)*X0 ; writes xs1 = fp16(X1*dinv), out[:,64:128]=relu(X1)
__global__ void __launch_bounds__(128)
k_apply1(const float* __restrict__ feat, const float* __restrict__ lam,
         float* __restrict__ out, int n) {
    int wp   = (blockIdx.x * blockDim.x + threadIdx.x) >> 5;
    int lane = threadIdx.x & 31;
    int g    = lane >> 3;
    int sl   = lane & 7;
    int w    = wp * 4 + g;                        // n divisible by 4
    if (wp * 4 >= n) return;
    unsigned gmask = 0xffu << (g * 8);
    float rn = 2.0f / __ldg(lam);
    float di = g_dinv[w];
    int  pad = __ldg(&g_degv[w]);
    int  pm  = max(pad, __shfl_xor_sync(0xffffffffu, pad, 8));
    pm       = max(pm,  __shfl_xor_sync(0xffffffffu, pm, 16));
    float2 a0 = {0.f,0.f}, a1 = {0.f,0.f}, a2 = {0.f,0.f}, a3 = {0.f,0.f};
    gather4(w, pad, pm, sl, gmask, g_xs0, a0, a1, a2, a3);
    const float4* fx0 = (const float4*)feat + (size_t)w * 16 + sl * 2;
    float4 xa = fx0[0], xb = fx0[1];
    float c1 = rn - 1.0f;
    float4 y0, y1;
    y0.x = -rn * (a0.x * di) + xa.x * c1;
    y0.y = -rn * (a0.y * di) + xa.y * c1;
    y0.z = -rn * (a1.x * di) + xa.z * c1;
    y0.w = -rn * (a1.y * di) + xa.w * c1;
    y1.x = -rn * (a2.x * di) + xb.x * c1;
    y1.y = -rn * (a2.y * di) + xb.y * c1;
    y1.z = -rn * (a3.x * di) + xb.z * c1;
    y1.w = -rn * (a3.y * di) + xb.w * c1;
    __half2 p0 = __floats2half2_rn(y0.x * di, y0.y * di);
    __half2 p1 = __floats2half2_rn(y0.z * di, y0.w * di);
    __half2 p2 = __floats2half2_rn(y1.x * di, y1.y * di);
    __half2 p3 = __floats2half2_rn(y1.z * di, y1.w * di);
    ((uint4*)g_xs1)[w * 8 + sl] =
        make_uint4(*(unsigned*)&p0, *(unsigned*)&p1, *(unsigned*)&p2, *(unsigned*)&p3);
    float4* o = (float4*)(out + (size_t)w * 192 + 64) + sl * 2;
    o[0] = make_float4(fmaxf(y0.x,0.f), fmaxf(y0.y,0.f), fmaxf(y0.z,0.f), fmaxf(y0.w,0.f));
    o[1] = make_float4(fmaxf(y1.x,0.f), fmaxf(y1.y,0.f), fmaxf(y1.z,0.f), fmaxf(y1.w,0.f));
}

// X2 = -2rn*h + 2(rn-1)*X1 - X0 ; X1 recovered as fp16(xs1)*sqrt(deg)
__global__ void __launch_bounds__(128)
k_apply2(const float* __restrict__ feat, const float* __restrict__ lam,
         float* __restrict__ out, int n) {
    int wp   = (blockIdx.x * blockDim.x + threadIdx.x) >> 5;
    int lane = threadIdx.x & 31;
    int g    = lane >> 3;
    int sl   = lane & 7;
    int w    = wp * 4 + g;
    if (wp * 4 >= n) return;
    unsigned gmask = 0xffu << (g * 8);
    float rn = 2.0f / __ldg(lam);
    float di = g_dinv[w];
    float ds = g_dsq[w];
    int  pad = __ldg(&g_degv[w]);
    int  pm  = max(pad, __shfl_xor_sync(0xffffffffu, pad, 8));
    pm       = max(pm,  __shfl_xor_sync(0xffffffffu, pm, 16));
    float2 a0 = {0.f,0.f}, a1 = {0.f,0.f}, a2 = {0.f,0.f}, a3 = {0.f,0.f};
    gather4(w, pad, pm, sl, gmask, g_xs1, a0, a1, a2, a3);
    const float4* fx0 = (const float4*)feat + (size_t)w * 16 + sl * 2;
    float4 xa = fx0[0], xb = fx0[1];
    uint4 xv = ((const uint4*)g_xs1)[w * 8 + sl];
    float2 s0 = __half22float2(u2h(xv.x));
    float2 s1 = __half22float2(u2h(xv.y));
    float2 s2 = __half22float2(u2h(xv.z));
    float2 s3 = __half22float2(u2h(xv.w));
    float c2 = 2.0f * (rn - 1.0f);
    float r2 = -2.0f * rn;
    float4 y0, y1;
    y0.x = r2 * (a0.x * di) + c2 * (s0.x * ds) - xa.x;
    y0.y = r2 * (a0.y * di) + c2 * (s0.y * ds) - xa.y;
    y0.z = r2 * (a1.x * di) + c2 * (s1.x * ds) - xa.z;
    y0.w = r2 * (a1.y * di) + c2 * (s1.y * ds) - xa.w;
    y1.x = r2 * (a2.x * di) + c2 * (s2.x * ds) - xb.x;
    y1.y = r2 * (a2.y * di) + c2 * (s2.y * ds) - xb.y;
    y1.z = r2 * (a3.x * di) + c2 * (s3.x * ds) - xb.z;
    y1.w = r2 * (a3.y * di) + c2 * (s3.y * ds) - xb.w;
    float4* o = (float4*)(out + (size_t)w * 192 + 128) + sl * 2;
    o[0] = make_float4(fmaxf(y0.x,0.f), fmaxf(y0.y,0.f), fmaxf(y0.z,0.f), fmaxf(y0.w,0.f));
    o[1] = make_float4(fmaxf(y1.x,0.f), fmaxf(y1.y,0.f), fmaxf(y1.z,0.f), fmaxf(y1.w,0.f));
}

// ---------------- launch ----------------
extern "C" void kernel_launch(void* const* d_in, const int* in_sizes, int n_in,
                              void* d_out, int out_size) {
    const float* feat = (const float*)d_in[0];
    const int*   src  = (const int*)d_in[1];
    const int*   dst  = (const int*)d_in[2];
    const float* lam  = (const float*)d_in[3];
    float* out = (float*)d_out;

    int n = in_sizes[0] / D;     // 60000
    int e = in_sizes[1];         // 1200000

    int eh = (e + 1) >> 1;
    int fmax = (n * 16 > eh) ? n * 16 : eh;
    k_fill_relu<<<(fmax + 255) / 256, 256>>>(src, dst, feat, out, e, n);

    int sthreads = n * 32;
    k_scale <<<(sthreads + 255) / 256, 256>>>(feat, n);

    int athreads = ((n + 3) / 4) * 32;            // 4 nodes per warp
    k_apply1<<<(athreads + 127) / 128, 128>>>(feat, lam, out, n);
    k_apply2<<<(athreads + 127) / 128, 128>>>(feat, lam, out, n);
}